// round 7
// baseline (speedup 1.0000x reference)
#include <cuda_runtime.h>
#include <stdint.h>

// Problem constants (shapes fixed by the dataset)
#define NN 100000
#define EE 3200000
#define DD 128     // input feature dim
#define F1 64      // hidden dim
#define SCAN_B 512 // scan block size (2^9)

// ---------------- device scratch (no allocation allowed) ----------------
__device__ int   g_is64;
__device__ int   g_cnt[NN];         // in-degree (real edges only)
__device__ int   g_off[NN];         // per-block-local exclusive prefix
__device__ int   g_bsum[256];       // scan block sums
__device__ int   g_rowptr[NN + 1];  // CSR row pointers (dst-major)
__device__ int   g_cursor[NN];      // fill cursors
__device__ int   g_csr[EE];         // CSR src indices
__device__ float g_dinv[NN];
__device__ __align__(16) float g_g1[NN * F1];  // UNSCALED y = x[v] @ W1
__device__ float g_g2[NN];                     // dinv[v] * (h[v] @ W2)

// ---------------- edge decode (int64 vs int32, runtime-detected) ----------------
__device__ __forceinline__ void load_edge(const void* __restrict__ e, int E, int i,
                                          int& s, int& d) {
    if (g_is64) {
        const long long* p = (const long long*)e;
        s = (int)p[i];
        d = (int)p[(long long)E + i];
    } else {
        const int* p = (const int*)e;
        s = p[i];
        d = p[E + i];
    }
}

// ---------------- K0: detect int64 vs int32 edge indices ----------------
__global__ void k_detect(const int* __restrict__ ew) {
    __shared__ int any;
    if (threadIdx.x == 0) any = 0;
    __syncthreads();
    int local = 0;
    for (int i = 1 + 2 * threadIdx.x; i < 4096; i += 2 * blockDim.x)
        if (ew[i] != 0) local = 1;
    if (local) atomicOr(&any, 1);
    __syncthreads();
    if (threadIdx.x == 0) g_is64 = (any == 0);
}

// ---------------- K1: zero the in-degree counters ----------------
__global__ void k_zero(int N) {
    int v = blockIdx.x * blockDim.x + threadIdx.x;
    if (v < N) g_cnt[v] = 0;
}

// ---------------- K2: count in-degrees (dst half only) ----------------
__global__ void k_count(const void* __restrict__ e, int E) {
    int i = blockIdx.x * blockDim.x + threadIdx.x;
    if (i >= E) return;
    int d;
    if (g_is64) d = ((const int*)e)[2 * ((long long)E + i)];  // low word, LE
    else        d = ((const int*)e)[E + i];
    atomicAdd(&g_cnt[d], 1);
}

// ---------------- K3a/b/c: exclusive prefix scan of g_cnt -> rowptr ----------------
__global__ void k_scan1(int N) {
    __shared__ int sm[SCAN_B];
    int v = blockIdx.x * SCAN_B + threadIdx.x;
    int c = (v < N) ? g_cnt[v] : 0;
    sm[threadIdx.x] = c;
    __syncthreads();
    int val = c;
    for (int o = 1; o < SCAN_B; o <<= 1) {
        int t = (threadIdx.x >= o) ? sm[threadIdx.x - o] : 0;
        __syncthreads();
        val += t;
        sm[threadIdx.x] = val;
        __syncthreads();
    }
    if (v < N) g_off[v] = val - c;                      // exclusive
    if (threadIdx.x == SCAN_B - 1) g_bsum[blockIdx.x] = val;
}
__global__ void k_scan2(int nb) {
    if (threadIdx.x == 0) {
        int run = 0;
        for (int b = 0; b < nb; b++) { int t = g_bsum[b]; g_bsum[b] = run; run += t; }
    }
}
__global__ void k_scan3(int N, int E) {
    int v = blockIdx.x * blockDim.x + threadIdx.x;
    if (v < N) {
        int rp = g_off[v] + g_bsum[v >> 9];
        g_rowptr[v] = rp;
        g_cursor[v] = rp;
        g_dinv[v]   = rsqrtf((float)(g_cnt[v] + 1));    // +1 self-loop
    }
    if (v == N) g_rowptr[N] = E;
}

// ---------------- K4: CSR fill (src index per dst slot) ----------------
__global__ void k_fill(const void* __restrict__ e, int E) {
    int i = blockIdx.x * blockDim.x + threadIdx.x;
    if (i >= E) return;
    int s, d;
    load_edge(e, E, i, s, d);
    int p = atomicAdd(&g_cursor[d], 1);
    g_csr[p] = s;
}

// ---------------- K5: g1 = x @ W1 (UNSCALED — no dinv dependency) ----------------
// 32 nodes per block, 256 threads. smem: W1 (32KB) + x tile (16KB) = 48KB.
// Runs on a second stream, overlapped with the CSR build.
__global__ void k_gemm(const float* __restrict__ x, const float* __restrict__ W1, int N) {
    __shared__ float ws[DD * F1];
    __shared__ float xs[32 * DD];
    int t = threadIdx.x;
    int base = blockIdx.x * 32;

    for (int i = t; i < DD * F1 / 4; i += 256)
        ((float4*)ws)[i] = ((const float4*)W1)[i];
    for (int i = t; i < 32 * DD / 4; i += 256) {
        int row = i >> 5, col = i & 31;
        float4 v = make_float4(0.f, 0.f, 0.f, 0.f);
        if (base + row < N) v = ((const float4*)x)[(size_t)(base + row) * 32 + col];
        ((float4*)xs)[i] = v;
    }
    __syncthreads();

    int jq = t & 15;
    int np = t >> 4;
    float4 a0 = make_float4(0.f, 0.f, 0.f, 0.f);
    float4 a1 = make_float4(0.f, 0.f, 0.f, 0.f);
    const float* xr0 = &xs[(2 * np) * DD];
    const float* xr1 = &xs[(2 * np + 1) * DD];

    #pragma unroll 4
    for (int k = 0; k < DD; k++) {
        float4 w = ((const float4*)ws)[k * 16 + jq];
        float x0 = xr0[k], x1 = xr1[k];
        a0.x = fmaf(x0, w.x, a0.x); a0.y = fmaf(x0, w.y, a0.y);
        a0.z = fmaf(x0, w.z, a0.z); a0.w = fmaf(x0, w.w, a0.w);
        a1.x = fmaf(x1, w.x, a1.x); a1.y = fmaf(x1, w.y, a1.y);
        a1.z = fmaf(x1, w.z, a1.z); a1.w = fmaf(x1, w.w, a1.w);
    }

    int n0 = base + 2 * np, n1 = n0 + 1;
    if (n0 < N) ((float4*)g_g1)[n0 * 16 + jq] = a0;
    if (n1 < N) ((float4*)g_g1)[n1 * 16 + jq] = a1;
}

// ---------------- K6: CSR gather layer 1 + per-edge dinv + epilogue + W2 proj ----------------
// Warp per node. Lane holds float2 column [2*lane, 2*lane+2) of the 64-wide row.
// Per edge: coalesced 256B row gather of y[src], FMA-scaled by dinv[src].
__global__ void __launch_bounds__(256, 8)
k_agg1(const float* __restrict__ b1, const float* __restrict__ W2, int N) {
    int w = (blockIdx.x * blockDim.x + threadIdx.x) >> 5;
    int lane = threadIdx.x & 31;
    if (w >= N) return;

    const float2* __restrict__ g1v = (const float2*)g_g1;
    float dvw = g_dinv[w];
    float2 self = __ldg(&g1v[w * 32 + lane]);
    float2 acc = make_float2(dvw * self.x, dvw * self.y);   // self-loop term
    int beg = g_rowptr[w], end = g_rowptr[w + 1];

    for (int base = beg; base < end; base += 32) {
        int idx = base + lane;
        int s = 0;
        float dv = 0.f;
        if (idx < end) {
            s  = __ldg(&g_csr[idx]);
            dv = __ldg(&g_dinv[s]);
        }
        int cnt = end - base;                               // uniform across warp
        if (cnt >= 32) {
            #pragma unroll
            for (int k = 0; k < 32; k++) {
                int   ss = __shfl_sync(0xffffffffu, s, k);
                float dd = __shfl_sync(0xffffffffu, dv, k);
                float2 v = __ldg(&g1v[ss * 32 + lane]);
                acc.x = fmaf(dd, v.x, acc.x);
                acc.y = fmaf(dd, v.y, acc.y);
            }
        } else {
            for (int k = 0; k < cnt; k++) {
                int   ss = __shfl_sync(0xffffffffu, s, k);
                float dd = __shfl_sync(0xffffffffu, dv, k);
                float2 v = __ldg(&g1v[ss * 32 + lane]);
                acc.x = fmaf(dd, v.x, acc.x);
                acc.y = fmaf(dd, v.y, acc.y);
            }
        }
    }

    // epilogue: h = relu(dinv*acc + b1); z = dinv * (h . W2)
    float2 bb = __ldg(&((const float2*)b1)[lane]);
    float2 ww = __ldg(&((const float2*)W2)[lane]);
    float h0 = fmaxf(fmaf(dvw, acc.x, bb.x), 0.f);
    float h1 = fmaxf(fmaf(dvw, acc.y, bb.y), 0.f);
    float p = h0 * ww.x + h1 * ww.y;
    #pragma unroll
    for (int o = 16; o > 0; o >>= 1) p += __shfl_xor_sync(0xffffffffu, p, o);
    if (lane == 0) g_g2[w] = dvw * p;
}

// ---------------- K7: CSR gather layer 2 + final bias (fused) ----------------
__global__ void k_agg2(const float* __restrict__ b2, float* __restrict__ out, int N) {
    int v = blockIdx.x * blockDim.x + threadIdx.x;
    if (v >= N) return;
    int beg = g_rowptr[v], end = g_rowptr[v + 1];
    float s0 = __ldg(&g_g2[v]), s1 = 0.f, s2 = 0.f, s3 = 0.f;  // self-loop + MLP=4
    int i = beg;
    for (; i + 4 <= end; i += 4) {
        int i0 = __ldg(&g_csr[i]);
        int i1 = __ldg(&g_csr[i + 1]);
        int i2 = __ldg(&g_csr[i + 2]);
        int i3 = __ldg(&g_csr[i + 3]);
        s0 += __ldg(&g_g2[i0]);
        s1 += __ldg(&g_g2[i1]);
        s2 += __ldg(&g_g2[i2]);
        s3 += __ldg(&g_g2[i3]);
    }
    for (; i < end; i++) s0 += __ldg(&g_g2[__ldg(&g_csr[i])]);
    out[v] = fmaf(g_dinv[v], (s0 + s1) + (s2 + s3), __ldg(b2));
}

// ---------------- launch (fork-join capture: gemm overlaps CSR build) ----------------
extern "C" void kernel_launch(void* const* d_in, const int* in_sizes, int n_in,
                              void* d_out, int out_size) {
    const float* x  = (const float*)d_in[0];
    const void*  e  = d_in[1];
    const float* W1 = (const float*)d_in[2];
    const float* b1 = (const float*)d_in[3];
    const float* W2 = (const float*)d_in[4];
    const float* b2 = (const float*)d_in[5];
    float* out = (float*)d_out;

    int N = in_sizes[0] / DD;   // 100000
    int E = in_sizes[1] / 2;    // 3200000
    int nb = (N + SCAN_B - 1) / SCAN_B;

    // One-time stream/event setup (no device memory involved). First call is
    // the correctness run (not capturing), so creation happens pre-capture.
    static cudaStream_t s2 = nullptr;
    static cudaEvent_t evFork = nullptr, evJoin = nullptr;
    if (s2 == nullptr) {
        cudaStreamCreateWithFlags(&s2, cudaStreamNonBlocking);
        cudaEventCreateWithFlags(&evFork, cudaEventDisableTiming);
        cudaEventCreateWithFlags(&evJoin, cudaEventDisableTiming);
    }

    // Fork: gemm (independent of edges/degrees) on s2.
    cudaEventRecord(evFork, 0);
    cudaStreamWaitEvent(s2, evFork, 0);
    k_gemm<<<(N + 31) / 32, 256, 0, s2>>>(x, W1, N);
    cudaEventRecord(evJoin, s2);

    // CSR build chain on the capture-origin stream.
    k_zero  <<<(N + 255) / 256, 256>>>(N);
    k_detect<<<1, 256>>>((const int*)e);
    k_count <<<(E + 255) / 256, 256>>>(e, E);
    k_scan1 <<<nb, SCAN_B>>>(N);
    k_scan2 <<<1, 32>>>(nb);
    k_scan3 <<<(N + 256) / 256, 256>>>(N, E);
    k_fill  <<<(E + 255) / 256, 256>>>(e, E);

    // Join: aggregation needs both gemm output and CSR.
    cudaStreamWaitEvent(0, evJoin, 0);
    k_agg1  <<<(N * 32 + 255) / 256, 256>>>(b1, W2, N);
    k_agg2  <<<(N + 255) / 256, 256>>>(b2, out, N);
}

// round 8
// speedup vs baseline: 1.1348x; 1.1348x over previous
#include <cuda_runtime.h>
#include <cuda_fp16.h>
#include <stdint.h>

// Problem constants (shapes fixed by the dataset)
#define NN 100000
#define EE 3200000
#define DD 128     // input feature dim
#define F1 64      // hidden dim
#define SCAN_B 512 // scan block size (2^9)

// ---------------- device scratch (no allocation allowed) ----------------
__device__ int     g_is64;
__device__ int     g_cnt[NN];         // in-degree (real edges only)
__device__ int     g_off[NN];         // per-block-local exclusive prefix
__device__ int     g_bsum[256];       // scan block sums
__device__ int     g_rowptr[NN + 1];  // CSR row pointers (dst-major)
__device__ int     g_cursor[NN];      // fill cursors
__device__ int     g_csr[EE];         // CSR src indices
__device__ float   g_dinv[NN];
__device__ __align__(16) __half2 g_h1[NN * 32];  // UNSCALED y = x@W1, fp16, 32 half2/row
__device__ float   g_g2[NN];                     // dinv[v] * (h[v] @ W2)

// ---------------- edge decode (int64 vs int32, runtime-detected) ----------------
__device__ __forceinline__ void load_edge(const void* __restrict__ e, int E, int i,
                                          int& s, int& d) {
    if (g_is64) {
        const long long* p = (const long long*)e;
        s = (int)p[i];
        d = (int)p[(long long)E + i];
    } else {
        const int* p = (const int*)e;
        s = p[i];
        d = p[E + i];
    }
}

// ---------------- K0: zero counters + detect int64 vs int32 ----------------
__global__ void k_prep(const int* __restrict__ ew, int N) {
    int v = blockIdx.x * blockDim.x + threadIdx.x;
    if (v < N) g_cnt[v] = 0;
    if (blockIdx.x == 0) {
        __shared__ int any;
        if (threadIdx.x == 0) any = 0;
        __syncthreads();
        int local = 0;
        for (int i = 1 + 2 * threadIdx.x; i < 4096; i += 2 * blockDim.x)
            if (ew[i] != 0) local = 1;
        if (local) atomicOr(&any, 1);
        __syncthreads();
        if (threadIdx.x == 0) g_is64 = (any == 0);
    }
}

// ---------------- K1: gemm (fp16 out) + fused in-degree count ----------------
// 32 nodes per block, 256 threads. smem: W1 (32KB) + x tile (16KB) = 48KB.
// Counter atomics are fire-and-forget REDs issued before the FMA loop; they
// drain while the FFMA pipe is busy.
__global__ void k_gemm(const float* __restrict__ x, const float* __restrict__ W1,
                       const void* __restrict__ e, int N, int E) {
    __shared__ float ws[DD * F1];
    __shared__ float xs[32 * DD];
    int t = threadIdx.x;
    int base = blockIdx.x * 32;

    // stage smem tiles (async-ish: issue loads first)
    for (int i = t; i < DD * F1 / 4; i += 256)
        ((float4*)ws)[i] = ((const float4*)W1)[i];
    for (int i = t; i < 32 * DD / 4; i += 256) {
        int row = i >> 5, col = i & 31;
        float4 v = make_float4(0.f, 0.f, 0.f, 0.f);
        if (base + row < N) v = ((const float4*)x)[(size_t)(base + row) * 32 + col];
        ((float4*)xs)[i] = v;
    }

    // fused degree count (dst half only; low words for int64)
    {
        int gtid = blockIdx.x * blockDim.x + t;
        int total = gridDim.x * blockDim.x;
        const int* ei = (const int*)e;
        bool is64 = (g_is64 != 0);
        for (int i = gtid; i < E; i += total) {
            int d = is64 ? ei[2 * ((long long)E + i)] : ei[E + i];
            atomicAdd(&g_cnt[d], 1);
        }
    }
    __syncthreads();

    int jq = t & 15;
    int np = t >> 4;
    float4 a0 = make_float4(0.f, 0.f, 0.f, 0.f);
    float4 a1 = make_float4(0.f, 0.f, 0.f, 0.f);
    const float* xr0 = &xs[(2 * np) * DD];
    const float* xr1 = &xs[(2 * np + 1) * DD];

    #pragma unroll 4
    for (int k = 0; k < DD; k++) {
        float4 w = ((const float4*)ws)[k * 16 + jq];
        float x0 = xr0[k], x1 = xr1[k];
        a0.x = fmaf(x0, w.x, a0.x); a0.y = fmaf(x0, w.y, a0.y);
        a0.z = fmaf(x0, w.z, a0.z); a0.w = fmaf(x0, w.w, a0.w);
        a1.x = fmaf(x1, w.x, a1.x); a1.y = fmaf(x1, w.y, a1.y);
        a1.z = fmaf(x1, w.z, a1.z); a1.w = fmaf(x1, w.w, a1.w);
    }

    int n0 = base + 2 * np, n1 = n0 + 1;
    if (n0 < N) {
        __half2 h[2] = { __floats2half2_rn(a0.x, a0.y), __floats2half2_rn(a0.z, a0.w) };
        *(uint2*)&g_h1[n0 * 32 + 2 * jq] = *(uint2*)h;
    }
    if (n1 < N) {
        __half2 h[2] = { __floats2half2_rn(a1.x, a1.y), __floats2half2_rn(a1.z, a1.w) };
        *(uint2*)&g_h1[n1 * 32 + 2 * jq] = *(uint2*)h;
    }
}

// ---------------- K2a/b/c: exclusive prefix scan of g_cnt -> rowptr ----------------
__global__ void k_scan1(int N) {
    __shared__ int sm[SCAN_B];
    int v = blockIdx.x * SCAN_B + threadIdx.x;
    int c = (v < N) ? g_cnt[v] : 0;
    sm[threadIdx.x] = c;
    __syncthreads();
    int val = c;
    for (int o = 1; o < SCAN_B; o <<= 1) {
        int t = (threadIdx.x >= o) ? sm[threadIdx.x - o] : 0;
        __syncthreads();
        val += t;
        sm[threadIdx.x] = val;
        __syncthreads();
    }
    if (v < N) g_off[v] = val - c;                      // exclusive
    if (threadIdx.x == SCAN_B - 1) g_bsum[blockIdx.x] = val;
}
__global__ void k_scan2(int nb) {
    if (threadIdx.x == 0) {
        int run = 0;
        for (int b = 0; b < nb; b++) { int t = g_bsum[b]; g_bsum[b] = run; run += t; }
    }
}
__global__ void k_scan3(int N, int E) {
    int v = blockIdx.x * blockDim.x + threadIdx.x;
    if (v < N) {
        int rp = g_off[v] + g_bsum[v >> 9];
        g_rowptr[v] = rp;
        g_cursor[v] = rp;
        g_dinv[v]   = rsqrtf((float)(g_cnt[v] + 1));    // +1 self-loop
    }
    if (v == N) g_rowptr[N] = E;
}

// ---------------- K3: CSR fill (src index per dst slot) ----------------
__global__ void k_fill(const void* __restrict__ e, int E) {
    int i = blockIdx.x * blockDim.x + threadIdx.x;
    if (i >= E) return;
    int s, d;
    load_edge(e, E, i, s, d);
    int p = atomicAdd(&g_cursor[d], 1);
    g_csr[p] = s;
}

// ---------------- K4: CSR gather L1 (fp16 rows) + per-edge dinv + epilogue + W2 ----------------
// Warp per node. Lane holds half2 column pair [2*lane, 2*lane+2).
// Per edge: one coalesced 128B row gather, FMA-scaled by dinv[src] in fp32.
__global__ void __launch_bounds__(256, 8)
k_agg1(const float* __restrict__ b1, const float* __restrict__ W2, int N) {
    int w = (blockIdx.x * blockDim.x + threadIdx.x) >> 5;
    int lane = threadIdx.x & 31;
    if (w >= N) return;

    float dvw = g_dinv[w];
    float2 self = __half22float2(__ldg(&g_h1[w * 32 + lane]));
    float2 acc = make_float2(dvw * self.x, dvw * self.y);   // self-loop term
    int beg = g_rowptr[w], end = g_rowptr[w + 1];

    for (int base = beg; base < end; base += 32) {
        int idx = base + lane;
        int s = 0;
        float dv = 0.f;
        if (idx < end) {
            s  = __ldg(&g_csr[idx]);
            dv = __ldg(&g_dinv[s]);
        }
        int cnt = end - base;                               // uniform across warp
        if (cnt >= 32) {
            #pragma unroll
            for (int k = 0; k < 32; k++) {
                int   ss = __shfl_sync(0xffffffffu, s, k);
                float dd = __shfl_sync(0xffffffffu, dv, k);
                float2 v = __half22float2(__ldg(&g_h1[ss * 32 + lane]));
                acc.x = fmaf(dd, v.x, acc.x);
                acc.y = fmaf(dd, v.y, acc.y);
            }
        } else {
            for (int k = 0; k < cnt; k++) {
                int   ss = __shfl_sync(0xffffffffu, s, k);
                float dd = __shfl_sync(0xffffffffu, dv, k);
                float2 v = __half22float2(__ldg(&g_h1[ss * 32 + lane]));
                acc.x = fmaf(dd, v.x, acc.x);
                acc.y = fmaf(dd, v.y, acc.y);
            }
        }
    }

    // epilogue: h = relu(dinv*acc + b1); z = dinv * (h . W2)
    float2 bb = __ldg(&((const float2*)b1)[lane]);
    float2 ww = __ldg(&((const float2*)W2)[lane]);
    float h0 = fmaxf(fmaf(dvw, acc.x, bb.x), 0.f);
    float h1 = fmaxf(fmaf(dvw, acc.y, bb.y), 0.f);
    float p = h0 * ww.x + h1 * ww.y;
    #pragma unroll
    for (int o = 16; o > 0; o >>= 1) p += __shfl_xor_sync(0xffffffffu, p, o);
    if (lane == 0) g_g2[w] = dvw * p;
}

// ---------------- K5: CSR gather layer 2 + final bias (fused) ----------------
__global__ void k_agg2(const float* __restrict__ b2, float* __restrict__ out, int N) {
    int v = blockIdx.x * blockDim.x + threadIdx.x;
    if (v >= N) return;
    int beg = g_rowptr[v], end = g_rowptr[v + 1];
    float s0 = __ldg(&g_g2[v]), s1 = 0.f, s2 = 0.f, s3 = 0.f;  // self-loop + MLP=4
    int i = beg;
    for (; i + 4 <= end; i += 4) {
        int i0 = __ldg(&g_csr[i]);
        int i1 = __ldg(&g_csr[i + 1]);
        int i2 = __ldg(&g_csr[i + 2]);
        int i3 = __ldg(&g_csr[i + 3]);
        s0 += __ldg(&g_g2[i0]);
        s1 += __ldg(&g_g2[i1]);
        s2 += __ldg(&g_g2[i2]);
        s3 += __ldg(&g_g2[i3]);
    }
    for (; i < end; i++) s0 += __ldg(&g_g2[__ldg(&g_csr[i])]);
    out[v] = fmaf(g_dinv[v], (s0 + s1) + (s2 + s3), __ldg(b2));
}

// ---------------- launch (single stream) ----------------
extern "C" void kernel_launch(void* const* d_in, const int* in_sizes, int n_in,
                              void* d_out, int out_size) {
    const float* x  = (const float*)d_in[0];
    const void*  e  = d_in[1];
    const float* W1 = (const float*)d_in[2];
    const float* b1 = (const float*)d_in[3];
    const float* W2 = (const float*)d_in[4];
    const float* b2 = (const float*)d_in[5];
    float* out = (float*)d_out;

    int N = in_sizes[0] / DD;   // 100000
    int E = in_sizes[1] / 2;    // 3200000
    int nb = (N + SCAN_B - 1) / SCAN_B;

    k_prep  <<<(N + 255) / 256, 256>>>((const int*)e, N);
    k_gemm  <<<(N + 31) / 32, 256>>>(x, W1, e, N, E);
    k_scan1 <<<nb, SCAN_B>>>(N);
    k_scan2 <<<1, 32>>>(nb);
    k_scan3 <<<(N + 256) / 256, 256>>>(N, E);
    k_fill  <<<(E + 255) / 256, 256>>>(e, E);
    k_agg1  <<<(N * 32 + 255) / 256, 256>>>(b1, W2, N);
    k_agg2  <<<(N + 255) / 256, 256>>>(b2, out, N);
}

// round 9
// speedup vs baseline: 1.4113x; 1.2436x over previous
#include <cuda_runtime.h>
#include <cuda_fp16.h>
#include <mma.h>
#include <stdint.h>

using namespace nvcuda;

// Problem constants (shapes fixed by the dataset)
#define NN 100000
#define EE 3200000
#define DD 128     // input feature dim
#define F1 64      // hidden dim
#define SCAN_B 512 // scan block size (2^9)
#define GM 64      // nodes per gemm block
#define LDA 136    // xs smem stride (halves, 272B: 16B-multiple)
#define LDB 72     // ws smem stride (halves, 144B: 16B-multiple)

// ---------------- device scratch (no allocation allowed) ----------------
__device__ int     g_is64;
__device__ int     g_cnt[NN];         // in-degree (real edges only)
__device__ int     g_off[NN];         // per-block-local exclusive prefix
__device__ int     g_bsum[256];       // scan block sums
__device__ int     g_rowptr[NN + 1];  // CSR row pointers (dst-major)
__device__ int     g_cursor[NN];      // fill cursors
__device__ int     g_csr[EE];         // CSR src indices
__device__ float   g_dinv[NN];
__device__ __align__(16) __half2 g_h1[NN * 32];  // UNSCALED y = x@W1, fp16, 32 half2/row
__device__ float   g_g2[NN];                     // dinv[v] * (h[v] @ W2)

// ---------------- edge decode (int64 vs int32, runtime-detected) ----------------
__device__ __forceinline__ void load_edge(const void* __restrict__ e, int E, int i,
                                          int& s, int& d) {
    if (g_is64) {
        const long long* p = (const long long*)e;
        s = (int)p[i];
        d = (int)p[(long long)E + i];
    } else {
        const int* p = (const int*)e;
        s = p[i];
        d = p[E + i];
    }
}

// ---------------- K0: zero counters + detect int64 vs int32 ----------------
__global__ void k_prep(const int* __restrict__ ew, int N) {
    int v = blockIdx.x * blockDim.x + threadIdx.x;
    if (v < N) g_cnt[v] = 0;
    if (blockIdx.x == 0) {
        __shared__ int any;
        if (threadIdx.x == 0) any = 0;
        __syncthreads();
        int local = 0;
        for (int i = 1 + 2 * threadIdx.x; i < 4096; i += 2 * blockDim.x)
            if (ew[i] != 0) local = 1;
        if (local) atomicOr(&any, 1);
        __syncthreads();
        if (threadIdx.x == 0) g_is64 = (any == 0);
    }
}

// ---------------- K1: HMMA gemm (fp16 in, fp32 acc, fp16 out) + fused count ----------------
// 64 nodes per block, 256 threads (8 warps). Warp w: m_tile = w&3, n_half = w>>2.
// The degree-count grid-stride loop runs first; its RED.ADDs drain under the MMA work.
__global__ void __launch_bounds__(256)
k_gemm(const float* __restrict__ x, const float* __restrict__ W1,
       const void* __restrict__ e, int N, int E) {
    __shared__ union {
        struct { __half xs[GM * LDA]; __half ws[DD * LDB]; } in;
        float outs[GM * F1];
    } sm;

    int t = threadIdx.x;
    int b0 = blockIdx.x * GM;

    // fused degree count (dst half only; low words for int64)
    {
        int gtid = blockIdx.x * blockDim.x + t;
        int total = gridDim.x * blockDim.x;
        const int* ei = (const int*)e;
        bool is64 = (g_is64 != 0);
        for (int i = gtid; i < E; i += total) {
            int d = is64 ? ei[2 * ((long long)E + i)] : ei[E + i];
            atomicAdd(&g_cnt[d], 1);
        }
    }

    // stage x tile (fp32 -> fp16): 64 rows x 128 cols = 2048 float4, 8 per thread
    for (int i = t; i < GM * DD / 4; i += 256) {
        int row = i >> 5, col = (i & 31) * 4;
        float4 v = make_float4(0.f, 0.f, 0.f, 0.f);
        if (b0 + row < N) v = ((const float4*)x)[(size_t)(b0 + row) * 32 + (i & 31)];
        __half2 h0 = __floats2half2_rn(v.x, v.y);
        __half2 h1 = __floats2half2_rn(v.z, v.w);
        *(__half2*)&sm.in.xs[row * LDA + col]     = h0;
        *(__half2*)&sm.in.xs[row * LDA + col + 2] = h1;
    }
    // stage W1 (fp32 -> fp16): 128 x 64 = 2048 float4
    for (int i = t; i < DD * F1 / 4; i += 256) {
        int row = i >> 4, col = (i & 15) * 4;
        float4 v = ((const float4*)W1)[i];
        __half2 h0 = __floats2half2_rn(v.x, v.y);
        __half2 h1 = __floats2half2_rn(v.z, v.w);
        *(__half2*)&sm.in.ws[row * LDB + col]     = h0;
        *(__half2*)&sm.in.ws[row * LDB + col + 2] = h1;
    }
    __syncthreads();

    int w = t >> 5;
    int m_tile = w & 3;   // 0..3 (16 rows each)
    int n_half = w >> 2;  // 0..1 (32 cols each -> two 16-col tiles)

    wmma::fragment<wmma::accumulator, 16, 16, 16, float> acc0, acc1;
    wmma::fill_fragment(acc0, 0.0f);
    wmma::fill_fragment(acc1, 0.0f);

    #pragma unroll
    for (int k = 0; k < DD; k += 16) {
        wmma::fragment<wmma::matrix_a, 16, 16, 16, __half, wmma::row_major> af;
        wmma::fragment<wmma::matrix_b, 16, 16, 16, __half, wmma::row_major> bf0, bf1;
        wmma::load_matrix_sync(af, &sm.in.xs[(m_tile * 16) * LDA + k], LDA);
        wmma::load_matrix_sync(bf0, &sm.in.ws[k * LDB + n_half * 32], LDB);
        wmma::load_matrix_sync(bf1, &sm.in.ws[k * LDB + n_half * 32 + 16], LDB);
        wmma::mma_sync(acc0, af, bf0, acc0);
        wmma::mma_sync(acc1, af, bf1, acc1);
    }
    __syncthreads();   // input tiles dead; reuse smem as fp32 staging

    wmma::store_matrix_sync(&sm.outs[(m_tile * 16) * F1 + n_half * 32], acc0, F1,
                            wmma::mem_row_major);
    wmma::store_matrix_sync(&sm.outs[(m_tile * 16) * F1 + n_half * 32 + 16], acc1, F1,
                            wmma::mem_row_major);
    __syncthreads();

    // write out as fp16 rows (64 halves = 128B per node)
    for (int i = t; i < GM * 32; i += 256) {
        int r = i >> 5, c = i & 31;
        int node = b0 + r;
        if (node < N)
            g_h1[node * 32 + c] =
                __floats2half2_rn(sm.outs[r * F1 + 2 * c], sm.outs[r * F1 + 2 * c + 1]);
    }
}

// ---------------- K2a/b/c: exclusive prefix scan of g_cnt -> rowptr ----------------
__global__ void k_scan1(int N) {
    __shared__ int sm[SCAN_B];
    int v = blockIdx.x * SCAN_B + threadIdx.x;
    int c = (v < N) ? g_cnt[v] : 0;
    sm[threadIdx.x] = c;
    __syncthreads();
    int val = c;
    for (int o = 1; o < SCAN_B; o <<= 1) {
        int t = (threadIdx.x >= o) ? sm[threadIdx.x - o] : 0;
        __syncthreads();
        val += t;
        sm[threadIdx.x] = val;
        __syncthreads();
    }
    if (v < N) g_off[v] = val - c;                      // exclusive
    if (threadIdx.x == SCAN_B - 1) g_bsum[blockIdx.x] = val;
}
// parallel Hillis-Steele over <=256 block sums (exclusive, in place)
__global__ void k_scan2(int nb) {
    __shared__ int sm[256];
    int t = threadIdx.x;
    int v = (t < nb) ? g_bsum[t] : 0;
    sm[t] = v;
    __syncthreads();
    int val = v;
    for (int o = 1; o < 256; o <<= 1) {
        int tt = (t >= o) ? sm[t - o] : 0;
        __syncthreads();
        val += tt;
        sm[t] = val;
        __syncthreads();
    }
    if (t < nb) g_bsum[t] = val - v;                    // exclusive
}
__global__ void k_scan3(int N, int E) {
    int v = blockIdx.x * blockDim.x + threadIdx.x;
    if (v < N) {
        int rp = g_off[v] + g_bsum[v >> 9];
        g_rowptr[v] = rp;
        g_cursor[v] = rp;
        g_dinv[v]   = rsqrtf((float)(g_cnt[v] + 1));    // +1 self-loop
    }
    if (v == N) g_rowptr[N] = E;
}

// ---------------- K3: CSR fill (src index per dst slot) ----------------
__global__ void k_fill(const void* __restrict__ e, int E) {
    int i = blockIdx.x * blockDim.x + threadIdx.x;
    if (i >= E) return;
    int s, d;
    load_edge(e, E, i, s, d);
    int p = atomicAdd(&g_cursor[d], 1);
    g_csr[p] = s;
}

// ---------------- K4: CSR gather L1 (fp16 rows) + per-edge dinv + epilogue + W2 ----------------
__global__ void __launch_bounds__(256, 8)
k_agg1(const float* __restrict__ b1, const float* __restrict__ W2, int N) {
    int w = (blockIdx.x * blockDim.x + threadIdx.x) >> 5;
    int lane = threadIdx.x & 31;
    if (w >= N) return;

    float dvw = g_dinv[w];
    float2 self = __half22float2(__ldg(&g_h1[w * 32 + lane]));
    float2 acc = make_float2(dvw * self.x, dvw * self.y);   // self-loop term
    int beg = g_rowptr[w], end = g_rowptr[w + 1];

    for (int base = beg; base < end; base += 32) {
        int idx = base + lane;
        int s = 0;
        float dv = 0.f;
        if (idx < end) {
            s  = __ldg(&g_csr[idx]);
            dv = __ldg(&g_dinv[s]);
        }
        int cnt = end - base;                               // uniform across warp
        if (cnt >= 32) {
            #pragma unroll
            for (int k = 0; k < 32; k++) {
                int   ss = __shfl_sync(0xffffffffu, s, k);
                float dd = __shfl_sync(0xffffffffu, dv, k);
                float2 v = __half22float2(__ldg(&g_h1[ss * 32 + lane]));
                acc.x = fmaf(dd, v.x, acc.x);
                acc.y = fmaf(dd, v.y, acc.y);
            }
        } else {
            for (int k = 0; k < cnt; k++) {
                int   ss = __shfl_sync(0xffffffffu, s, k);
                float dd = __shfl_sync(0xffffffffu, dv, k);
                float2 v = __half22float2(__ldg(&g_h1[ss * 32 + lane]));
                acc.x = fmaf(dd, v.x, acc.x);
                acc.y = fmaf(dd, v.y, acc.y);
            }
        }
    }

    // epilogue: h = relu(dinv*acc + b1); z = dinv * (h . W2)
    float2 bb = __ldg(&((const float2*)b1)[lane]);
    float2 ww = __ldg(&((const float2*)W2)[lane]);
    float h0 = fmaxf(fmaf(dvw, acc.x, bb.x), 0.f);
    float h1 = fmaxf(fmaf(dvw, acc.y, bb.y), 0.f);
    float p = h0 * ww.x + h1 * ww.y;
    #pragma unroll
    for (int o = 16; o > 0; o >>= 1) p += __shfl_xor_sync(0xffffffffu, p, o);
    if (lane == 0) g_g2[w] = dvw * p;
}

// ---------------- K5: CSR gather layer 2 + final bias (fused) ----------------
__global__ void k_agg2(const float* __restrict__ b2, float* __restrict__ out, int N) {
    int v = blockIdx.x * blockDim.x + threadIdx.x;
    if (v >= N) return;
    int beg = g_rowptr[v], end = g_rowptr[v + 1];
    float s0 = __ldg(&g_g2[v]), s1 = 0.f, s2 = 0.f, s3 = 0.f;  // self-loop + MLP=4
    int i = beg;
    for (; i + 4 <= end; i += 4) {
        int i0 = __ldg(&g_csr[i]);
        int i1 = __ldg(&g_csr[i + 1]);
        int i2 = __ldg(&g_csr[i + 2]);
        int i3 = __ldg(&g_csr[i + 3]);
        s0 += __ldg(&g_g2[i0]);
        s1 += __ldg(&g_g2[i1]);
        s2 += __ldg(&g_g2[i2]);
        s3 += __ldg(&g_g2[i3]);
    }
    for (; i < end; i++) s0 += __ldg(&g_g2[__ldg(&g_csr[i])]);
    out[v] = fmaf(g_dinv[v], (s0 + s1) + (s2 + s3), __ldg(b2));
}

// ---------------- launch (single stream) ----------------
extern "C" void kernel_launch(void* const* d_in, const int* in_sizes, int n_in,
                              void* d_out, int out_size) {
    const float* x  = (const float*)d_in[0];
    const void*  e  = d_in[1];
    const float* W1 = (const float*)d_in[2];
    const float* b1 = (const float*)d_in[3];
    const float* W2 = (const float*)d_in[4];
    const float* b2 = (const float*)d_in[5];
    float* out = (float*)d_out;

    int N = in_sizes[0] / DD;   // 100000
    int E = in_sizes[1] / 2;    // 3200000
    int nb = (N + SCAN_B - 1) / SCAN_B;

    k_prep  <<<(N + 255) / 256, 256>>>((const int*)e, N);
    k_gemm  <<<(N + GM - 1) / GM, 256>>>(x, W1, e, N, E);
    k_scan1 <<<nb, SCAN_B>>>(N);
    k_scan2 <<<1, 256>>>(nb);
    k_scan3 <<<(N + 256) / 256, 256>>>(N, E);
    k_fill  <<<(E + 255) / 256, 256>>>(e, E);
    k_agg1  <<<(N * 32 + 255) / 256, 256>>>(b1, W2, N);
    k_agg2  <<<(N + 255) / 256, 256>>>(b2, out, N);
}